// round 6
// baseline (speedup 1.0000x reference)
#include <cuda_runtime.h>
#include <cstdint>

#define Bb   8
#define Nn   1024
#define Cc   512
#define Kk   20
#define Mm   64
#define Pp   (Bb * Nn)        // 8192 points
#define CNT1 (Pp * Kk)        // 163840 samples for BN1
#define CNT2 Pp               // 8192 samples for BN2
#define EPS  1e-5f

// Scratch (no cudaMalloc allowed)
__device__ float g_y[Pp * 128];         // per-point y1(0:64) | y2(64:128)
__device__ float g_hmax[Pp * 64];
__device__ float g_hmin[Pp * 64];
__device__ float g_part1[128 * 256];    // transposed: [col(sum64|sq64)][block 256]
__device__ float g_bn1[128];            // scale(64) | bias(64)
__device__ float g_p2s[512 * 128];      // transposed: [col][by 128]
__device__ float g_p2q[512 * 128];
__device__ float g_bn2[1024];           // scale(512) | bias(512)
__device__ int   g_cntB = 0;
__device__ int   g_cntC = 0;

__device__ __forceinline__ float tf32_rna(float v) {
    uint32_t u;
    asm("cvt.rna.tf32.f32 %0, %1;" : "=r"(u) : "f"(v));
    return __uint_as_float(u);
}

__device__ __forceinline__ void mma_tf32(float* d, const float* a, const float* b) {
    asm volatile(
        "mma.sync.aligned.m16n8k8.row.col.f32.tf32.tf32.f32 "
        "{%0,%1,%2,%3}, {%4,%5,%6,%7}, {%8,%9}, {%0,%1,%2,%3};"
        : "+f"(d[0]), "+f"(d[1]), "+f"(d[2]), "+f"(d[3])
        : "r"(__float_as_uint(a[0])), "r"(__float_as_uint(a[1])),
          "r"(__float_as_uint(a[2])), "r"(__float_as_uint(a[3])),
          "r"(__float_as_uint(b[0])), "r"(__float_as_uint(b[1])));
}

__device__ __forceinline__ void tf32_split(float v, float& hi, float& lo) {
    hi = tf32_rna(v);
    lo = tf32_rna(v - hi);
}

// ---------------------------------------------------------------------------
// kA: fused fold(W1) + GEMM1: y[8192][128] = x @ W1'^T, tf32 MMA, double-buffered
// Block: 64 pts x 128 N, BK=16, 256 threads (8 warps, 32x32 each), grid=128
// ---------------------------------------------------------------------------
__global__ void __launch_bounds__(256) kA_gemm1(const float* __restrict__ x,
                                                const float* __restrict__ W1) {
    __shared__ float sx[2][64][20];
    __shared__ float sw[2][128][20];

    int tid = threadIdx.x;
    int lane = tid & 31, w = tid >> 5;
    int grp = lane >> 2, tig = lane & 3;
    int m_base = (w >> 2) * 32;
    int n_base = (w & 3) * 32;
    int p0 = blockIdx.x * 64;

    int xrow = tid >> 2;            // 0..63 (also folded-W row m)
    int cseg = (tid & 3) * 4;       // 0,4,8,12

    float acc[2][4][4];
#pragma unroll
    for (int r = 0; r < 2; r++)
#pragma unroll
        for (int j = 0; j < 4; j++)
#pragma unroll
            for (int q = 0; q < 4; q++) acc[r][j][q] = 0.f;

    float4 rx, rw0, rw1;
    // prefetch tile 0
    {
        int k0 = 0;
        rx  = *reinterpret_cast<const float4*>(&x[(p0 + xrow) * 512 + k0 + cseg]);
        rw0 = *reinterpret_cast<const float4*>(&W1[xrow * 1024 + k0 + cseg]);
        float4 a = *reinterpret_cast<const float4*>(&W1[xrow * 1024 + 512 + k0 + cseg]);
        rw1 = make_float4(a.x - rw0.x, a.y - rw0.y, a.z - rw0.z, a.w - rw0.w);
    }
    *reinterpret_cast<float4*>(&sx[0][xrow][cseg]) = rx;
    *reinterpret_cast<float4*>(&sw[0][xrow][cseg]) = rw0;
    *reinterpret_cast<float4*>(&sw[0][xrow + 64][cseg]) = rw1;
    __syncthreads();

    int cur = 0;
    for (int t = 0; t < 32; t++) {
        if (t < 31) {
            int k0 = (t + 1) * 16;
            rx  = *reinterpret_cast<const float4*>(&x[(p0 + xrow) * 512 + k0 + cseg]);
            rw0 = *reinterpret_cast<const float4*>(&W1[xrow * 1024 + k0 + cseg]);
            float4 a = *reinterpret_cast<const float4*>(&W1[xrow * 1024 + 512 + k0 + cseg]);
            rw1 = make_float4(a.x - rw0.x, a.y - rw0.y, a.z - rw0.z, a.w - rw0.w);
        }
        // compute from smem[cur]
#pragma unroll
        for (int ks = 0; ks < 16; ks += 8) {
            float ah[2][4], al[2][4], bh[4][2], bl[4][2];
#pragma unroll
            for (int r = 0; r < 2; r++) {
                int mr = m_base + r * 16;
                tf32_split(sx[cur][mr + grp][ks + tig],       ah[r][0], al[r][0]);
                tf32_split(sx[cur][mr + grp + 8][ks + tig],   ah[r][1], al[r][1]);
                tf32_split(sx[cur][mr + grp][ks + tig + 4],   ah[r][2], al[r][2]);
                tf32_split(sx[cur][mr + grp + 8][ks + tig + 4], ah[r][3], al[r][3]);
            }
#pragma unroll
            for (int j = 0; j < 4; j++) {
                int nc = n_base + j * 8 + grp;
                tf32_split(sw[cur][nc][ks + tig],     bh[j][0], bl[j][0]);
                tf32_split(sw[cur][nc][ks + tig + 4], bh[j][1], bl[j][1]);
            }
#pragma unroll
            for (int r = 0; r < 2; r++)
#pragma unroll
                for (int j = 0; j < 4; j++) {
                    mma_tf32(acc[r][j], ah[r], bh[j]);
                    mma_tf32(acc[r][j], al[r], bh[j]);
                    mma_tf32(acc[r][j], ah[r], bl[j]);
                }
        }
        if (t < 31) {
            int nxt = cur ^ 1;
            *reinterpret_cast<float4*>(&sx[nxt][xrow][cseg]) = rx;
            *reinterpret_cast<float4*>(&sw[nxt][xrow][cseg]) = rw0;
            *reinterpret_cast<float4*>(&sw[nxt][xrow + 64][cseg]) = rw1;
            __syncthreads();
            cur = nxt;
        }
    }

#pragma unroll
    for (int r = 0; r < 2; r++) {
        int prow = p0 + m_base + r * 16 + grp;
#pragma unroll
        for (int j = 0; j < 4; j++) {
            int col = n_base + j * 8 + 2 * tig;
            *reinterpret_cast<float2*>(&g_y[prow * 128 + col]) =
                make_float2(acc[r][j][0], acc[r][j][1]);
            *reinterpret_cast<float2*>(&g_y[(prow + 8) * 128 + col]) =
                make_float2(acc[r][j][2], acc[r][j][3]);
        }
    }
}

// ---------------------------------------------------------------------------
// kB: gather (max/min + sum/sumsq) + last-block BN1 finalize. grid=256, 256thr
// ---------------------------------------------------------------------------
__global__ void __launch_bounds__(256) kB_gather(const int* __restrict__ idx,
                                                 const float* __restrict__ gamma1,
                                                 const float* __restrict__ beta1) {
    __shared__ int   sidx[640];
    __shared__ float red[2][256];
    __shared__ float tot2[256];
    __shared__ bool  islast;

    int tid = threadIdx.x;
    int pbase = blockIdx.x * 32;
    for (int i = tid; i < 640; i += 256) sidx[i] = idx[pbase * 20 + i];
    __syncthreads();

    int m = tid & 63, slot = tid >> 6;
    float fs = 0.f, fq = 0.f;
#pragma unroll
    for (int i = 0; i < 8; i++) {
        int pl = slot * 8 + i;
        int p = pbase + pl;
        float y2 = g_y[p * 128 + 64 + m];
        int rowb = (p & ~1023) * 128;
        const int* ip = &sidx[pl * 20];
        float vmax = -1e30f, vmin = 1e30f;
#pragma unroll
        for (int k = 0; k < 20; k++) {
            float v = g_y[rowb + ip[k] * 128 + m] + y2;
            fs += v;
            fq += v * v;
            vmax = fmaxf(vmax, v);
            vmin = fminf(vmin, v);
        }
        g_hmax[p * 64 + m] = vmax;
        g_hmin[p * 64 + m] = vmin;
    }
    red[0][tid] = fs;
    red[1][tid] = fq;
    __syncthreads();
    if (tid < 64) {
        float s = red[0][tid] + red[0][tid + 64] + red[0][tid + 128] + red[0][tid + 192];
        float q = red[1][tid] + red[1][tid + 64] + red[1][tid + 128] + red[1][tid + 192];
        g_part1[tid * 256 + blockIdx.x] = s;          // transposed
        g_part1[(64 + tid) * 256 + blockIdx.x] = q;
    }
    __threadfence();
    __syncthreads();
    if (tid == 0) {
        int old = atomicAdd(&g_cntB, 1);
        islast = (old == 255);
    }
    __syncthreads();
    if (!islast) return;
    __threadfence();

    // tail: 128 cols x 256 entries; col = tid&127, half = tid>>7
    {
        int col = tid & 127, half = tid >> 7;
        const float4* p4 = reinterpret_cast<const float4*>(&g_part1[col * 256 + half * 128]);
        float s = 0.f;
#pragma unroll 8
        for (int r = 0; r < 32; r++) {
            float4 v = p4[r];
            s += v.x + v.y + v.z + v.w;
        }
        red[0][tid] = s;
    }
    __syncthreads();
    if (tid < 128) tot2[tid] = red[0][tid] + red[0][tid + 128];
    __syncthreads();
    if (tid < 64) {
        float inv = 1.f / (float)CNT1;
        float mu = tot2[tid] * inv;
        float var = tot2[64 + tid] * inv - mu * mu;
        float sc = gamma1[tid] * rsqrtf(var + EPS);
        g_bn1[tid] = sc;
        g_bn1[64 + tid] = beta1[tid] - mu * sc;
        if (tid == 0) g_cntB = 0;    // reset for next graph replay
    }
}

// ---------------------------------------------------------------------------
// kC: tf32 GEMM2 (BN1-apply+leaky prologue) + BN2 partial stats + last-block
//     BN2 finalize. Block: 64p x 128d, K=64, 256 thr, grid (4,128)
// ---------------------------------------------------------------------------
__global__ void __launch_bounds__(256) kC_gemm2(const float* __restrict__ W2,
                                                const float* __restrict__ gamma2,
                                                const float* __restrict__ beta2,
                                                float* __restrict__ out) {
    __shared__ float sv[64][68];
    __shared__ float sw[128][20];
    __shared__ float sbn[128];
    __shared__ float ssum[8][32];
    __shared__ float ssq[8][32];
    __shared__ bool  islast;

    int tid = threadIdx.x;
    int lane = tid & 31, w = tid >> 5;
    int grp = lane >> 2, tig = lane & 3;
    int m_base = (w >> 2) * 32;
    int n_base = (w & 3) * 32;
    int d0 = blockIdx.x * 128, p0 = blockIdx.y * 64;

    if (tid < 128) sbn[tid] = g_bn1[tid];
    __syncthreads();

#pragma unroll
    for (int i = 0; i < 16; i++) {
        int e = tid + i * 256;
        int pt = e >> 6, m = e & 63;
        float sc = sbn[m], bi = sbn[64 + m];
        float h = (sc >= 0.f) ? g_hmax[(p0 + pt) * 64 + m] : g_hmin[(p0 + pt) * 64 + m];
        float v = sc * h + bi;
        sv[pt][m] = fmaxf(v, 0.2f * v);
    }

    float acc[2][4][4];
#pragma unroll
    for (int r = 0; r < 2; r++)
#pragma unroll
        for (int j = 0; j < 4; j++)
#pragma unroll
            for (int q = 0; q < 4; q++) acc[r][j][q] = 0.f;

    for (int t = 0; t < 4; t++) {
        int k0 = t * 16;
        {
            int wrow = tid >> 1;
            int seg = (tid & 1) * 8;
            *reinterpret_cast<float4*>(&sw[wrow][seg]) =
                *reinterpret_cast<const float4*>(&W2[(d0 + wrow) * 64 + k0 + seg]);
            *reinterpret_cast<float4*>(&sw[wrow][seg + 4]) =
                *reinterpret_cast<const float4*>(&W2[(d0 + wrow) * 64 + k0 + seg + 4]);
        }
        __syncthreads();
#pragma unroll
        for (int ks = 0; ks < 16; ks += 8) {
            float ah[2][4], al[2][4], bh[4][2], bl[4][2];
#pragma unroll
            for (int r = 0; r < 2; r++) {
                int mr = m_base + r * 16;
                tf32_split(sv[mr + grp][k0 + ks + tig],         ah[r][0], al[r][0]);
                tf32_split(sv[mr + grp + 8][k0 + ks + tig],     ah[r][1], al[r][1]);
                tf32_split(sv[mr + grp][k0 + ks + tig + 4],     ah[r][2], al[r][2]);
                tf32_split(sv[mr + grp + 8][k0 + ks + tig + 4], ah[r][3], al[r][3]);
            }
#pragma unroll
            for (int j = 0; j < 4; j++) {
                int nc = n_base + j * 8 + grp;
                tf32_split(sw[nc][ks + tig],     bh[j][0], bl[j][0]);
                tf32_split(sw[nc][ks + tig + 4], bh[j][1], bl[j][1]);
            }
#pragma unroll
            for (int r = 0; r < 2; r++)
#pragma unroll
                for (int j = 0; j < 4; j++) {
                    mma_tf32(acc[r][j], ah[r], bh[j]);
                    mma_tf32(acc[r][j], al[r], bh[j]);
                    mma_tf32(acc[r][j], ah[r], bl[j]);
                }
        }
        __syncthreads();
    }

    // epilogue stores + per-thread column sums (8 cols each)
    float ts[8], tq[8];
#pragma unroll
    for (int i = 0; i < 8; i++) { ts[i] = 0.f; tq[i] = 0.f; }
#pragma unroll
    for (int r = 0; r < 2; r++) {
        int prow = p0 + m_base + r * 16 + grp;
#pragma unroll
        for (int j = 0; j < 4; j++) {
            int col = d0 + n_base + j * 8 + 2 * tig;
            *reinterpret_cast<float2*>(&out[prow * 512 + col]) =
                make_float2(acc[r][j][0], acc[r][j][1]);
            *reinterpret_cast<float2*>(&out[(prow + 8) * 512 + col]) =
                make_float2(acc[r][j][2], acc[r][j][3]);
#pragma unroll
            for (int q = 0; q < 2; q++) {
                float a0 = acc[r][j][q], a1 = acc[r][j][2 + q];
                ts[j * 2 + q] += a0 + a1;
                tq[j * 2 + q] += a0 * a0 + a1 * a1;
            }
        }
    }
    // reduce over grp (lane bits [2:4]) via shfl
#pragma unroll
    for (int i = 0; i < 8; i++) {
#pragma unroll
        for (int off = 4; off < 32; off <<= 1) {
            ts[i] += __shfl_xor_sync(0xffffffffu, ts[i], off);
            tq[i] += __shfl_xor_sync(0xffffffffu, tq[i], off);
        }
    }
    if (lane < 4) {
#pragma unroll
        for (int j = 0; j < 4; j++)
#pragma unroll
            for (int q = 0; q < 2; q++) {
                ssum[w][j * 8 + 2 * lane + q] = ts[j * 2 + q];
                ssq[w][j * 8 + 2 * lane + q]  = tq[j * 2 + q];
            }
    }
    __syncthreads();
    if (tid < 128) {
        int g = tid >> 5, c = tid & 31;
        float s = ssum[g][c] + ssum[g + 4][c];
        float q = ssq[g][c] + ssq[g + 4][c];
        int col = d0 + g * 32 + c;
        g_p2s[col * 128 + blockIdx.y] = s;
        g_p2q[col * 128 + blockIdx.y] = q;
    }
    __threadfence();
    __syncthreads();
    if (tid == 0) {
        int old = atomicAdd(&g_cntC, 1);
        islast = (old == 511);
    }
    __syncthreads();
    if (!islast) return;
    __threadfence();

    // tail: 512 cols x 128 rows; each thread handles cols tid and tid+256
#pragma unroll
    for (int cc = 0; cc < 2; cc++) {
        int col = tid + cc * 256;
        const float4* p4s = reinterpret_cast<const float4*>(&g_p2s[col * 128]);
        const float4* p4q = reinterpret_cast<const float4*>(&g_p2q[col * 128]);
        float s = 0.f, q = 0.f;
#pragma unroll 8
        for (int r = 0; r < 32; r++) {
            float4 a = p4s[r];
            float4 b = p4q[r];
            s += a.x + a.y + a.z + a.w;
            q += b.x + b.y + b.z + b.w;
        }
        float inv = 1.f / (float)CNT2;
        float mu = s * inv;
        float var = q * inv - mu * mu;
        float sc = gamma2[col] * rsqrtf(var + EPS);
        g_bn2[col] = sc;
        g_bn2[512 + col] = beta2[col] - mu * sc;
    }
    if (tid == 0) g_cntC = 0;    // reset for next graph replay
}

// ---------------------------------------------------------------------------
// kD: in-place affine + leaky on out (float4 vectorized)
// ---------------------------------------------------------------------------
__global__ void __launch_bounds__(256) kD_final(float* __restrict__ out) {
    int i = blockIdx.x * 256 + threadIdx.x;
    float4 v = reinterpret_cast<float4*>(out)[i];
    int d = (i * 4) & 511;
    float s0 = g_bn2[d],       s1 = g_bn2[d + 1],   s2 = g_bn2[d + 2],   s3 = g_bn2[d + 3];
    float b0 = g_bn2[512 + d], b1 = g_bn2[513 + d], b2 = g_bn2[514 + d], b3 = g_bn2[515 + d];
    float t0 = s0 * v.x + b0;
    float t1 = s1 * v.y + b1;
    float t2 = s2 * v.z + b2;
    float t3 = s3 * v.w + b3;
    v.x = fmaxf(t0, 0.2f * t0);
    v.y = fmaxf(t1, 0.2f * t1);
    v.z = fmaxf(t2, 0.2f * t2);
    v.w = fmaxf(t3, 0.2f * t3);
    reinterpret_cast<float4*>(out)[i] = v;
}

// ---------------------------------------------------------------------------
extern "C" void kernel_launch(void* const* d_in, const int* in_sizes, int n_in,
                              void* d_out, int out_size) {
    const float* x      = (const float*)d_in[0];
    const int*   idx    = (const int*)  d_in[1];
    const float* W1     = (const float*)d_in[2];
    const float* gamma1 = (const float*)d_in[3];
    const float* beta1  = (const float*)d_in[4];
    const float* W2     = (const float*)d_in[5];
    const float* gamma2 = (const float*)d_in[6];
    const float* beta2  = (const float*)d_in[7];
    float* out = (float*)d_out;

    kA_gemm1<<<128, 256>>>(x, W1);
    kB_gather<<<256, 256>>>(idx, gamma1, beta1);
    kC_gemm2<<<dim3(4, 128), 256>>>(W2, gamma2, beta2, out);
    kD_final<<<4096, 256>>>(out);
}

// round 7
// speedup vs baseline: 1.0619x; 1.0619x over previous
#include <cuda_runtime.h>
#include <cstdint>

#define Bb   8
#define Nn   1024
#define Cc   512
#define Kk   20
#define Mm   64
#define Pp   (Bb * Nn)        // 8192 points
#define CNT1 (Pp * Kk)        // 163840 samples for BN1
#define CNT2 Pp               // 8192 samples for BN2
#define EPS  1e-5f

// Scratch (no cudaMalloc allowed)
__device__ float g_y[Pp * 128];         // per-point y1(0:64) | y2(64:128)
__device__ float g_hmax[Pp * 64];
__device__ float g_hmin[Pp * 64];
__device__ float g_part1[128 * 256];    // transposed: [col(sum64|sq64)][block 256]
__device__ float g_bn1[128];            // scale(64) | bias(64)
__device__ float g_p2s[512 * 128];      // transposed: [col][ptile 128]
__device__ float g_p2q[512 * 128];
__device__ float g_bn2[1024];           // scale(512) | bias(512)
__device__ int   g_cntB = 0;
__device__ int   g_cntC = 0;
__device__ int   g_cntD = 0;
__device__ int   g_flagC = 0;

__device__ __forceinline__ float tf32_rna(float v) {
    uint32_t u;
    asm("cvt.rna.tf32.f32 %0, %1;" : "=r"(u) : "f"(v));
    return __uint_as_float(u);
}

__device__ __forceinline__ void mma_tf32(float* d, const float* a, const float* b) {
    asm volatile(
        "mma.sync.aligned.m16n8k8.row.col.f32.tf32.tf32.f32 "
        "{%0,%1,%2,%3}, {%4,%5,%6,%7}, {%8,%9}, {%0,%1,%2,%3};"
        : "+f"(d[0]), "+f"(d[1]), "+f"(d[2]), "+f"(d[3])
        : "r"(__float_as_uint(a[0])), "r"(__float_as_uint(a[1])),
          "r"(__float_as_uint(a[2])), "r"(__float_as_uint(a[3])),
          "r"(__float_as_uint(b[0])), "r"(__float_as_uint(b[1])));
}

__device__ __forceinline__ void tf32_split(float v, float& hi, float& lo) {
    hi = tf32_rna(v);
    lo = tf32_rna(v - hi);
}

// ---------------------------------------------------------------------------
// kA: fused fold(W1) + GEMM1: y[8192][128] = x @ W1'^T, tf32 MMA, double-buffered
// ---------------------------------------------------------------------------
__global__ void __launch_bounds__(256) kA_gemm1(const float* __restrict__ x,
                                                const float* __restrict__ W1) {
    __shared__ float sx[2][64][20];
    __shared__ float sw[2][128][20];

    int tid = threadIdx.x;
    int lane = tid & 31, w = tid >> 5;
    int grp = lane >> 2, tig = lane & 3;
    int m_base = (w >> 2) * 32;
    int n_base = (w & 3) * 32;
    int p0 = blockIdx.x * 64;

    int xrow = tid >> 2;
    int cseg = (tid & 3) * 4;

    float acc[2][4][4];
#pragma unroll
    for (int r = 0; r < 2; r++)
#pragma unroll
        for (int j = 0; j < 4; j++)
#pragma unroll
            for (int q = 0; q < 4; q++) acc[r][j][q] = 0.f;

    float4 rx, rw0, rw1;
    {
        rx  = *reinterpret_cast<const float4*>(&x[(p0 + xrow) * 512 + cseg]);
        rw0 = *reinterpret_cast<const float4*>(&W1[xrow * 1024 + cseg]);
        float4 a = *reinterpret_cast<const float4*>(&W1[xrow * 1024 + 512 + cseg]);
        rw1 = make_float4(a.x - rw0.x, a.y - rw0.y, a.z - rw0.z, a.w - rw0.w);
    }
    *reinterpret_cast<float4*>(&sx[0][xrow][cseg]) = rx;
    *reinterpret_cast<float4*>(&sw[0][xrow][cseg]) = rw0;
    *reinterpret_cast<float4*>(&sw[0][xrow + 64][cseg]) = rw1;
    __syncthreads();

    int cur = 0;
    for (int t = 0; t < 32; t++) {
        if (t < 31) {
            int k0 = (t + 1) * 16;
            rx  = *reinterpret_cast<const float4*>(&x[(p0 + xrow) * 512 + k0 + cseg]);
            rw0 = *reinterpret_cast<const float4*>(&W1[xrow * 1024 + k0 + cseg]);
            float4 a = *reinterpret_cast<const float4*>(&W1[xrow * 1024 + 512 + k0 + cseg]);
            rw1 = make_float4(a.x - rw0.x, a.y - rw0.y, a.z - rw0.z, a.w - rw0.w);
        }
#pragma unroll
        for (int ks = 0; ks < 16; ks += 8) {
            float ah[2][4], al[2][4], bh[4][2], bl[4][2];
#pragma unroll
            for (int r = 0; r < 2; r++) {
                int mr = m_base + r * 16;
                tf32_split(sx[cur][mr + grp][ks + tig],         ah[r][0], al[r][0]);
                tf32_split(sx[cur][mr + grp + 8][ks + tig],     ah[r][1], al[r][1]);
                tf32_split(sx[cur][mr + grp][ks + tig + 4],     ah[r][2], al[r][2]);
                tf32_split(sx[cur][mr + grp + 8][ks + tig + 4], ah[r][3], al[r][3]);
            }
#pragma unroll
            for (int j = 0; j < 4; j++) {
                int nc = n_base + j * 8 + grp;
                tf32_split(sw[cur][nc][ks + tig],     bh[j][0], bl[j][0]);
                tf32_split(sw[cur][nc][ks + tig + 4], bh[j][1], bl[j][1]);
            }
#pragma unroll
            for (int r = 0; r < 2; r++)
#pragma unroll
                for (int j = 0; j < 4; j++) {
                    mma_tf32(acc[r][j], ah[r], bh[j]);
                    mma_tf32(acc[r][j], al[r], bh[j]);
                    mma_tf32(acc[r][j], ah[r], bl[j]);
                }
        }
        if (t < 31) {
            int nxt = cur ^ 1;
            *reinterpret_cast<float4*>(&sx[nxt][xrow][cseg]) = rx;
            *reinterpret_cast<float4*>(&sw[nxt][xrow][cseg]) = rw0;
            *reinterpret_cast<float4*>(&sw[nxt][xrow + 64][cseg]) = rw1;
            __syncthreads();
            cur = nxt;
        }
    }

#pragma unroll
    for (int r = 0; r < 2; r++) {
        int prow = p0 + m_base + r * 16 + grp;
#pragma unroll
        for (int j = 0; j < 4; j++) {
            int col = n_base + j * 8 + 2 * tig;
            *reinterpret_cast<float2*>(&g_y[prow * 128 + col]) =
                make_float2(acc[r][j][0], acc[r][j][1]);
            *reinterpret_cast<float2*>(&g_y[(prow + 8) * 128 + col]) =
                make_float2(acc[r][j][2], acc[r][j][3]);
        }
    }
}

// ---------------------------------------------------------------------------
// kB: gather (max/min + sum/sumsq) + last-block BN1 finalize. grid=256, 256thr
// ---------------------------------------------------------------------------
__global__ void __launch_bounds__(256) kB_gather(const int* __restrict__ idx,
                                                 const float* __restrict__ gamma1,
                                                 const float* __restrict__ beta1) {
    __shared__ int   sidx[640];
    __shared__ float red[2][256];
    __shared__ float tot2[256];
    __shared__ bool  islast;

    int tid = threadIdx.x;
    int pbase = blockIdx.x * 32;
    for (int i = tid; i < 640; i += 256) sidx[i] = idx[pbase * 20 + i];
    __syncthreads();

    int m = tid & 63, slot = tid >> 6;
    float fs = 0.f, fq = 0.f;
#pragma unroll
    for (int i = 0; i < 8; i++) {
        int pl = slot * 8 + i;
        int p = pbase + pl;
        float y2 = g_y[p * 128 + 64 + m];
        int rowb = (p & ~1023) * 128;
        const int* ip = &sidx[pl * 20];
        float vmax = -1e30f, vmin = 1e30f;
#pragma unroll
        for (int k = 0; k < 20; k++) {
            float v = g_y[rowb + ip[k] * 128 + m] + y2;
            fs += v;
            fq += v * v;
            vmax = fmaxf(vmax, v);
            vmin = fminf(vmin, v);
        }
        g_hmax[p * 64 + m] = vmax;
        g_hmin[p * 64 + m] = vmin;
    }
    red[0][tid] = fs;
    red[1][tid] = fq;
    __syncthreads();
    if (tid < 64) {
        float s = red[0][tid] + red[0][tid + 64] + red[0][tid + 128] + red[0][tid + 192];
        float q = red[1][tid] + red[1][tid + 64] + red[1][tid + 128] + red[1][tid + 192];
        g_part1[tid * 256 + blockIdx.x] = s;
        g_part1[(64 + tid) * 256 + blockIdx.x] = q;
    }
    __threadfence();
    __syncthreads();
    if (tid == 0) {
        int old = atomicAdd(&g_cntB, 1);
        islast = (old == 255);
    }
    __syncthreads();
    if (!islast) return;
    __threadfence();

    {
        int col = tid & 127, half = tid >> 7;
        const float4* p4 = reinterpret_cast<const float4*>(&g_part1[col * 256 + half * 128]);
        float s = 0.f;
#pragma unroll 8
        for (int r = 0; r < 32; r++) {
            float4 v = p4[r];
            s += v.x + v.y + v.z + v.w;
        }
        red[0][tid] = s;
    }
    __syncthreads();
    if (tid < 128) tot2[tid] = red[0][tid] + red[0][tid + 128];
    __syncthreads();
    if (tid < 64) {
        float inv = 1.f / (float)CNT1;
        float mu = tot2[tid] * inv;
        float var = tot2[64 + tid] * inv - mu * mu;
        float sc = gamma1[tid] * rsqrtf(var + EPS);
        g_bn1[tid] = sc;
        g_bn1[64 + tid] = beta1[tid] - mu * sc;
        if (tid == 0) g_cntB = 0;
    }
}

// ---------------------------------------------------------------------------
// kC: terminal kernel. grid (4,64), 256 thr, 2 blocks/SM -> all 256 resident.
// Each block: two p-tiles (y, y+64) of GEMM2 with accs in regs; BN2 partial
// stats; grid barrier (counter+flag); last block finalizes BN2; all blocks
// then apply affine+leaky from regs and store final out ONCE.
// ---------------------------------------------------------------------------
__global__ void __launch_bounds__(256, 2) kC_gemm2(const float* __restrict__ W2,
                                                   const float* __restrict__ gamma2,
                                                   const float* __restrict__ beta2,
                                                   float* __restrict__ out) {
    __shared__ float sv[2][64][68];   // activations for both p-tiles
    __shared__ float sw[128][20];     // W2 k-tile
    __shared__ float sbn[128];
    __shared__ float ssum[8][32];
    __shared__ float ssq[8][32];
    __shared__ bool  islast;

    int tid = threadIdx.x;
    int lane = tid & 31, w = tid >> 5;
    int grp = lane >> 2, tig = lane & 3;
    int m_base = (w >> 2) * 32;
    int n_base = (w & 3) * 32;
    int d0 = blockIdx.x * 128;
    int y = blockIdx.y;               // 0..63; tiles y and y+64

    if (tid < 128) sbn[tid] = g_bn1[tid];
    __syncthreads();

    // build both activation tiles
#pragma unroll
    for (int t2 = 0; t2 < 2; t2++) {
        int p0 = (y + t2 * 64) * 64;
#pragma unroll
        for (int i = 0; i < 16; i++) {
            int e = tid + i * 256;
            int pt = e >> 6, m = e & 63;
            float sc = sbn[m], bi = sbn[64 + m];
            float h = (sc >= 0.f) ? g_hmax[(p0 + pt) * 64 + m] : g_hmin[(p0 + pt) * 64 + m];
            float v = sc * h + bi;
            sv[t2][pt][m] = fmaxf(v, 0.2f * v);
        }
    }

    float acc[2][2][4][4];            // [tile][r][j][q]
#pragma unroll
    for (int t2 = 0; t2 < 2; t2++)
#pragma unroll
        for (int r = 0; r < 2; r++)
#pragma unroll
            for (int j = 0; j < 4; j++)
#pragma unroll
                for (int q = 0; q < 4; q++) acc[t2][r][j][q] = 0.f;

    for (int t = 0; t < 4; t++) {
        int k0 = t * 16;
        {
            int wrow = tid >> 1;
            int seg = (tid & 1) * 8;
            *reinterpret_cast<float4*>(&sw[wrow][seg]) =
                *reinterpret_cast<const float4*>(&W2[(d0 + wrow) * 64 + k0 + seg]);
            *reinterpret_cast<float4*>(&sw[wrow][seg + 4]) =
                *reinterpret_cast<const float4*>(&W2[(d0 + wrow) * 64 + k0 + seg + 4]);
        }
        __syncthreads();
#pragma unroll
        for (int ks = 0; ks < 16; ks += 8) {
            float bh[4][2], bl[4][2];
#pragma unroll
            for (int j = 0; j < 4; j++) {
                int nc = n_base + j * 8 + grp;
                tf32_split(sw[nc][ks + tig],     bh[j][0], bl[j][0]);
                tf32_split(sw[nc][ks + tig + 4], bh[j][1], bl[j][1]);
            }
#pragma unroll
            for (int t2 = 0; t2 < 2; t2++) {
                float ah[2][4], al[2][4];
#pragma unroll
                for (int r = 0; r < 2; r++) {
                    int mr = m_base + r * 16;
                    tf32_split(sv[t2][mr + grp][k0 + ks + tig],         ah[r][0], al[r][0]);
                    tf32_split(sv[t2][mr + grp + 8][k0 + ks + tig],     ah[r][1], al[r][1]);
                    tf32_split(sv[t2][mr + grp][k0 + ks + tig + 4],     ah[r][2], al[r][2]);
                    tf32_split(sv[t2][mr + grp + 8][k0 + ks + tig + 4], ah[r][3], al[r][3]);
                }
#pragma unroll
                for (int r = 0; r < 2; r++)
#pragma unroll
                    for (int j = 0; j < 4; j++) {
                        mma_tf32(acc[t2][r][j], ah[r], bh[j]);
                        mma_tf32(acc[t2][r][j], al[r], bh[j]);
                        mma_tf32(acc[t2][r][j], ah[r], bl[j]);
                    }
            }
        }
        __syncthreads();
    }

    // BN2 partial stats for both tiles
#pragma unroll
    for (int t2 = 0; t2 < 2; t2++) {
        float ts[8], tq[8];
#pragma unroll
        for (int i = 0; i < 8; i++) { ts[i] = 0.f; tq[i] = 0.f; }
#pragma unroll
        for (int r = 0; r < 2; r++)
#pragma unroll
            for (int j = 0; j < 4; j++)
#pragma unroll
                for (int q = 0; q < 2; q++) {
                    float a0 = acc[t2][r][j][q], a1 = acc[t2][r][j][2 + q];
                    ts[j * 2 + q] += a0 + a1;
                    tq[j * 2 + q] += a0 * a0 + a1 * a1;
                }
#pragma unroll
        for (int i = 0; i < 8; i++) {
#pragma unroll
            for (int off = 4; off < 32; off <<= 1) {
                ts[i] += __shfl_xor_sync(0xffffffffu, ts[i], off);
                tq[i] += __shfl_xor_sync(0xffffffffu, tq[i], off);
            }
        }
        if (lane < 4) {
#pragma unroll
            for (int j = 0; j < 4; j++)
#pragma unroll
                for (int q = 0; q < 2; q++) {
                    ssum[w][j * 8 + 2 * lane + q] = ts[j * 2 + q];
                    ssq[w][j * 8 + 2 * lane + q]  = tq[j * 2 + q];
                }
        }
        __syncthreads();
        if (tid < 128) {
            int g = tid >> 5, c = tid & 31;
            float s = ssum[g][c] + ssum[g + 4][c];
            float q = ssq[g][c] + ssq[g + 4][c];
            int col = d0 + g * 32 + c;
            g_p2s[col * 128 + y + t2 * 64] = s;
            g_p2q[col * 128 + y + t2 * 64] = q;
        }
        __syncthreads();
    }

    // --- grid barrier: counter, last block finalizes BN2, flag release ---
    __threadfence();
    __syncthreads();
    if (tid == 0) {
        int old = atomicAdd(&g_cntC, 1);
        islast = (old == 255);
    }
    __syncthreads();
    if (islast) {
        __threadfence();
#pragma unroll
        for (int cc = 0; cc < 2; cc++) {
            int col = tid + cc * 256;
            const float4* p4s = reinterpret_cast<const float4*>(&g_p2s[col * 128]);
            const float4* p4q = reinterpret_cast<const float4*>(&g_p2q[col * 128]);
            float s = 0.f, q = 0.f;
#pragma unroll 8
            for (int r = 0; r < 32; r++) {
                float4 a = p4s[r];
                float4 b = p4q[r];
                s += a.x + a.y + a.z + a.w;
                q += b.x + b.y + b.z + b.w;
            }
            float inv = 1.f / (float)CNT2;
            float mu = s * inv;
            float var = q * inv - mu * mu;
            float sc = gamma2[col] * rsqrtf(var + EPS);
            g_bn2[col] = sc;
            g_bn2[512 + col] = beta2[col] - mu * sc;
        }
        __threadfence();
        __syncthreads();
        if (tid == 0) atomicExch(&g_flagC, 1);
    }
    // spin until BN2 ready
    if (tid == 0) {
        while (atomicAdd(&g_flagC, 0) == 0) __nanosleep(64);
    }
    __syncthreads();
    __threadfence();

    // --- apply BN2 affine + leaky from registers, store final out ---
    float scv[4][2], biv[4][2];
#pragma unroll
    for (int j = 0; j < 4; j++) {
        int col = d0 + n_base + j * 8 + 2 * tig;
        scv[j][0] = g_bn2[col];
        scv[j][1] = g_bn2[col + 1];
        biv[j][0] = g_bn2[512 + col];
        biv[j][1] = g_bn2[513 + col];
    }
#pragma unroll
    for (int t2 = 0; t2 < 2; t2++) {
        int p0 = (y + t2 * 64) * 64;
#pragma unroll
        for (int r = 0; r < 2; r++) {
            int prow = p0 + m_base + r * 16 + grp;
#pragma unroll
            for (int j = 0; j < 4; j++) {
                int col = d0 + n_base + j * 8 + 2 * tig;
                float v0 = scv[j][0] * acc[t2][r][j][0] + biv[j][0];
                float v1 = scv[j][1] * acc[t2][r][j][1] + biv[j][1];
                float v2 = scv[j][0] * acc[t2][r][j][2] + biv[j][0];
                float v3 = scv[j][1] * acc[t2][r][j][3] + biv[j][1];
                v0 = fmaxf(v0, 0.2f * v0);
                v1 = fmaxf(v1, 0.2f * v1);
                v2 = fmaxf(v2, 0.2f * v2);
                v3 = fmaxf(v3, 0.2f * v3);
                *reinterpret_cast<float2*>(&out[prow * 512 + col]) = make_float2(v0, v1);
                *reinterpret_cast<float2*>(&out[(prow + 8) * 512 + col]) = make_float2(v2, v3);
            }
        }
    }

    // reset counters for next graph replay (last finisher)
    __threadfence();
    __syncthreads();
    if (tid == 0) {
        int old = atomicAdd(&g_cntD, 1);
        if (old == 255) {
            g_cntC = 0;
            g_cntD = 0;
            g_flagC = 0;
        }
    }
}

// ---------------------------------------------------------------------------
extern "C" void kernel_launch(void* const* d_in, const int* in_sizes, int n_in,
                              void* d_out, int out_size) {
    const float* x      = (const float*)d_in[0];
    const int*   idx    = (const int*)  d_in[1];
    const float* W1     = (const float*)d_in[2];
    const float* gamma1 = (const float*)d_in[3];
    const float* beta1  = (const float*)d_in[4];
    const float* W2     = (const float*)d_in[5];
    const float* gamma2 = (const float*)d_in[6];
    const float* beta2  = (const float*)d_in[7];
    float* out = (float*)d_out;

    kA_gemm1<<<128, 256>>>(x, W1);
    kB_gather<<<256, 256>>>(idx, gamma1, beta1);
    kC_gemm2<<<dim3(4, 64), 256>>>(W2, gamma2, beta2, out);
}